// round 16
// baseline (speedup 1.0000x reference)
#include <cuda_runtime.h>
#include <math.h>

#define DIM 4096
#define DIAG_BLOCKS 4       // 4 * 1024 threads = 4096 diagonal elements
#define FILL_BLOCKS 4096    // 4096 * 1024 threads * 16 B = 64 MiB exactly

// First 30 primes (== P_DIAG for DIM=4096).
__constant__ int c_primes[30] = {
    2, 3, 5, 7, 11, 13, 17, 19, 23, 29,
    31, 37, 41, 43, 47, 53, 59, 61, 67, 71,
    73, 79, 83, 89, 97, 101, 103, 107, 109, 113};

// ---------------------------------------------------------------------------
// ONE kernel, ZERO synchronization, disjoint writes (R15 structure), with
// 1024-thread blocks: same per-warp store pattern (contiguous 512 B STG.128),
// but 4100 blocks instead of 16416 — targeting the measured ~190 cyc/block
// churn that R15's profile says is the limiter (L1 55%, L2 48%, issue 21%:
// nothing saturated; time scales with block count).
//  * Blocks [0, 4): fp32 diagonal (fp64 phase reduction), one elem/thread,
//    wave-1 resident so the compute hides under the fill.
//  * Blocks [4, 4100): zero fill, 1 float4/thread, store predicated OFF for
//    the 4096 diagonal-containing slots (disjoint from diag writes).
//
// Math reduction (validated R5-R15, rel_err 2.46e-6):
//  * Off-diagonal prime terms are purely imaginary -> cancel EXACTLY under
//    0.5*(H + H^dagger); Re(H) (float32 output) is a pure diagonal.
//  * reg ~3.6e-18 additively invisible in float32 -> reduction dropped.
// ---------------------------------------------------------------------------
__global__ __launch_bounds__(1024)
void build_kernel(const float* sr_p, const float* si_p, const float* th_p,
                  float4* __restrict__ out) {
    const unsigned int bid = blockIdx.x;

    if (bid >= DIAG_BLOCKS) {
        // -------- streaming zero fill (skip diagonal slots) --------
        const unsigned int idx = (bid - DIAG_BLOCKS) * 1024u + threadIdx.x;
        const unsigned int row = idx >> 10;     // 1024 float4 per matrix row
        const unsigned int col4 = idx & 1023u;
        if (col4 != (row >> 2)) {
            out[idx] = make_float4(0.f, 0.f, 0.f, 0.f);
        }
        return;
    }

    // -------- diagonal writer blocks (wave-1 resident) --------
    const unsigned int t = bid * 1024u + threadIdx.x;  // 0..4095
    const int n = (int)t + 1;                          // 1..4096

    const float sr = sr_p ? *sr_p : 0.5f;
    const float si = si_p ? *si_p : 14.134725141734693f;
    const float th = th_p ? *th_p : 1e-22f;

    const float logn = logf((float)n);
    const float amp = expf(-sr * logn);        // n^(-sr)

    // Phase si*ln(n) reaches ~118 rad: fp64 product + fp64 2*pi range
    // reduction to [-pi,pi], then fp32 cosine (accurate on reduced arg).
    const double phi = (double)si * (double)logn;
    const double kq = rint(phi * 0.15915494309189533576);   // 1/(2*pi)
    const float r = (float)(phi - kq * 6.2831853071795864769);
    const float c = cosf(r);

    const bool in_range = (fabsf(sr) < 30.0f) && (fabsf(si) < 500.0f);
    const bool safe = (-sr * logn) > -80.0f;
    // CUTOFF 1e-80 underflows to 0 in fp32, matching the reference's own
    // complex128 -> float32 lowering.
    float d = (in_range || safe) ? amp * c : 0.0f;

    if (n <= 113) {
        bool isp = false;
#pragma unroll
        for (int j = 0; j < 30; j++) isp = isp || (n == c_primes[j]);
        if (isp) {
            const float corr = fminf(sqrtf(sr * sr + si * si), 5.0f);
            const float ZETA2 = 1.6449340668482264f;  // pi^2/6
            d += th * logn * corr * (ZETA2 / (float)n);
        }
    }

    // Write the diagonal-containing float4 slot (disjoint from fill writes).
    float4 v = make_float4(0.f, 0.f, 0.f, 0.f);
    switch (t & 3u) {
        case 0:  v.x = d; break;
        case 1:  v.y = d; break;
        case 2:  v.z = d; break;
        default: v.w = d; break;
    }
    out[(size_t)t * 1024u + (t >> 2)] = v;
}

extern "C" void kernel_launch(void* const* d_in, const int* in_sizes, int n_in,
                              void* d_out, int out_size) {
    (void)in_sizes; (void)out_size;
    const float* sr = (n_in >= 1) ? (const float*)d_in[0] : 0;
    const float* si = (n_in >= 2) ? (const float*)d_in[1] : 0;
    const float* th = (n_in >= 3) ? (const float*)d_in[2] : 0;

    build_kernel<<<DIAG_BLOCKS + FILL_BLOCKS, 1024>>>(sr, si, th,
                                                      (float4*)d_out);
}

// round 17
// speedup vs baseline: 1.0175x; 1.0175x over previous
#include <cuda_runtime.h>
#include <math.h>

#define DIM 4096
#define DIAG_BLOCKS 4       // 4 * 1024 threads = 4096 diagonal elements
#define FILL_BLOCKS 2048    // 2048 blocks * 1024 thr * 2 float4 = 64 MiB

// First 30 primes (== P_DIAG for DIM=4096).
__constant__ int c_primes[30] = {
    2, 3, 5, 7, 11, 13, 17, 19, 23, 29,
    31, 37, 41, 43, 47, 53, 59, 61, 67, 71,
    73, 79, 83, 89, 97, 101, 103, 107, 109, 113};

// ---------------------------------------------------------------------------
// ONE kernel, ZERO synchronization, disjoint writes. R16 structure with the
// one remaining unsampled variable: TWO independent float4 stores per thread
// (warp-contiguous at idx and idx+1024), doubling per-warp store MLP while
// halving warp count. Everything else is the proven configuration:
//  * Blocks [0, 4): fp32 diagonal (fp64 phase reduction), wave-1 resident.
//  * Blocks [4, 2052): zero fill, stores predicated OFF for the 4096
//    diagonal-containing slots (disjoint from diag writes).
//
// Math reduction (validated R5-R16, rel_err 2.46e-6):
//  * Off-diagonal prime terms are purely imaginary -> cancel EXACTLY under
//    0.5*(H + H^dagger); Re(H) (float32 output) is a pure diagonal.
//  * reg ~3.6e-18 additively invisible in float32 -> reduction dropped.
// ---------------------------------------------------------------------------
__global__ __launch_bounds__(1024)
void build_kernel(const float* sr_p, const float* si_p, const float* th_p,
                  float4* __restrict__ out) {
    const unsigned int bid = blockIdx.x;

    if (bid >= DIAG_BLOCKS) {
        // ---- streaming zero fill: 2 warp-contiguous float4 per thread ----
        const unsigned int idx0 =
            (bid - DIAG_BLOCKS) * 2048u + threadIdx.x;   // slot 1
        const unsigned int idx1 = idx0 + 1024u;          // slot 2

        const unsigned int row0 = idx0 >> 10;
        const unsigned int row1 = idx1 >> 10;
        const bool diag0 = ((idx0 & 1023u) == (row0 >> 2));
        const bool diag1 = ((idx1 & 1023u) == (row1 >> 2));

        const float4 z = make_float4(0.f, 0.f, 0.f, 0.f);
        if (!diag0) out[idx0] = z;
        if (!diag1) out[idx1] = z;
        return;
    }

    // -------- diagonal writer blocks (wave-1 resident) --------
    const unsigned int t = bid * 1024u + threadIdx.x;  // 0..4095
    const int n = (int)t + 1;                          // 1..4096

    const float sr = sr_p ? *sr_p : 0.5f;
    const float si = si_p ? *si_p : 14.134725141734693f;
    const float th = th_p ? *th_p : 1e-22f;

    const float logn = logf((float)n);
    const float amp = expf(-sr * logn);        // n^(-sr)

    // Phase si*ln(n) reaches ~118 rad: fp64 product + fp64 2*pi range
    // reduction to [-pi,pi], then fp32 cosine (accurate on reduced arg).
    const double phi = (double)si * (double)logn;
    const double kq = rint(phi * 0.15915494309189533576);   // 1/(2*pi)
    const float r = (float)(phi - kq * 6.2831853071795864769);
    const float c = cosf(r);

    const bool in_range = (fabsf(sr) < 30.0f) && (fabsf(si) < 500.0f);
    const bool safe = (-sr * logn) > -80.0f;
    // CUTOFF 1e-80 underflows to 0 in fp32, matching the reference's own
    // complex128 -> float32 lowering.
    float d = (in_range || safe) ? amp * c : 0.0f;

    if (n <= 113) {
        bool isp = false;
#pragma unroll
        for (int j = 0; j < 30; j++) isp = isp || (n == c_primes[j]);
        if (isp) {
            const float corr = fminf(sqrtf(sr * sr + si * si), 5.0f);
            const float ZETA2 = 1.6449340668482264f;  // pi^2/6
            d += th * logn * corr * (ZETA2 / (float)n);
        }
    }

    // Write the diagonal-containing float4 slot (disjoint from fill writes).
    float4 v = make_float4(0.f, 0.f, 0.f, 0.f);
    switch (t & 3u) {
        case 0:  v.x = d; break;
        case 1:  v.y = d; break;
        case 2:  v.z = d; break;
        default: v.w = d; break;
    }
    out[(size_t)t * 1024u + (t >> 2)] = v;
}

extern "C" void kernel_launch(void* const* d_in, const int* in_sizes, int n_in,
                              void* d_out, int out_size) {
    (void)in_sizes; (void)out_size;
    const float* sr = (n_in >= 1) ? (const float*)d_in[0] : 0;
    const float* si = (n_in >= 2) ? (const float*)d_in[1] : 0;
    const float* th = (n_in >= 3) ? (const float*)d_in[2] : 0;

    build_kernel<<<DIAG_BLOCKS + FILL_BLOCKS, 1024>>>(sr, si, th,
                                                      (float4*)d_out);
}